// round 5
// baseline (speedup 1.0000x reference)
#include <cuda_runtime.h>
#include <cuda_bf16.h>
#include <cstdint>

#define B_  512
#define M_  16
#define D_  128
#define P_  16
#define T_  4096
#define R_  (B_*M_)          // 8192 rows
#define TMT 128              // CTA tile rows
#define TNT 128              // CTA tile cols

// ---- device-global scratch (no allocations allowed) ----
__device__ __nv_bfloat16 g_nsh[R_ * D_];
__device__ __nv_bfloat16 g_nsl[R_ * D_];
__device__ __nv_bfloat16 g_tjh[T_ * D_];
__device__ __nv_bfloat16 g_tjl[T_ * D_];
__device__ float g_ssq[R_];
__device__ float g_tsq[T_];

// ---------------------------------------------------------------- helpers
__device__ __forceinline__ uint32_t smem_u32(const void* p) {
    uint32_t a;
    asm("{ .reg .u64 t; cvta.to.shared.u64 t, %1; cvt.u32.u64 %0, t; }" : "=r"(a) : "l"(p));
    return a;
}
__device__ __forceinline__ float ex2a(float x) {
    float r; asm("ex2.approx.f32 %0, %1;" : "=f"(r) : "f"(x)); return r;
}
__device__ __forceinline__ void cpasync16(uint32_t s, const void* g) {
    asm volatile("cp.async.cg.shared.global [%0], [%1], 16;" :: "r"(s), "l"(g));
}
#define CP_COMMIT() asm volatile("cp.async.commit_group;" ::: "memory")
#define CP_WAIT(n)  asm volatile("cp.async.wait_group %0;" :: "n"(n) : "memory")

__device__ __forceinline__ void ldsm4(uint32_t* r, uint32_t a) {
    asm volatile("ldmatrix.sync.aligned.m8n8.x4.shared.b16 {%0,%1,%2,%3}, [%4];"
        : "=r"(r[0]), "=r"(r[1]), "=r"(r[2]), "=r"(r[3]) : "r"(a));
}
__device__ __forceinline__ void mma_bf16(float* d, const uint32_t* a, const uint32_t* b) {
    asm volatile(
        "mma.sync.aligned.m16n8k16.row.col.f32.bf16.bf16.f32 "
        "{%0,%1,%2,%3}, {%4,%5,%6,%7}, {%8,%9}, {%0,%1,%2,%3};"
        : "+f"(d[0]), "+f"(d[1]), "+f"(d[2]), "+f"(d[3])
        : "r"(a[0]), "r"(a[1]), "r"(a[2]), "r"(a[3]), "r"(b[0]), "r"(b[1]));
}

// ---------------------------------------------------------------------------
// Kernel 1 (fused): blockIdx.x < 32  -> new_state (16 batches/block) + split + ssq
//                   blockIdx.x >= 32 -> trajectory hi/lo split + tsq
// grid dim3(48, 16), 128 threads.
// ---------------------------------------------------------------------------
__global__ __launch_bounds__(128) void prep_kernel(
    const float* __restrict__ phi, const float* __restrict__ state,
    const float* __restrict__ A,   const float* __restrict__ Bin,
    const float* __restrict__ tj,  float* __restrict__ tail)
{
    if (blockIdx.x >= 32) {
        // ---- trajectory part: 256 logical blocks, 16 rows each, 4 warps
        const int blk = blockIdx.y * 16 + (blockIdx.x - 32);
        const int wrp = threadIdx.x >> 5;
        const int lid = threadIdx.x & 31;
#pragma unroll
        for (int rr = 0; rr < 4; rr++) {
            const int row = blk * 16 + wrp * 4 + rr;
            float4 v = reinterpret_cast<const float4*>(tj)[row * 32 + lid];
            float f[4] = {v.x, v.y, v.z, v.w};
            uint32_t hp[2], lp[2];
#pragma unroll
            for (int j = 0; j < 2; j++) {
                __nv_bfloat16 h0 = __float2bfloat16_rn(f[2 * j]);
                __nv_bfloat16 h1 = __float2bfloat16_rn(f[2 * j + 1]);
                __nv_bfloat16 l0 = __float2bfloat16_rn(f[2 * j] - __bfloat162float(h0));
                __nv_bfloat16 l1 = __float2bfloat16_rn(f[2 * j + 1] - __bfloat162float(h1));
                hp[j] = (uint32_t)__bfloat16_as_ushort(h0) | ((uint32_t)__bfloat16_as_ushort(h1) << 16);
                lp[j] = (uint32_t)__bfloat16_as_ushort(l0) | ((uint32_t)__bfloat16_as_ushort(l1) << 16);
            }
            uint32_t* oh = reinterpret_cast<uint32_t*>(g_tjh) + row * 64 + lid * 2;
            uint32_t* ol = reinterpret_cast<uint32_t*>(g_tjl) + row * 64 + lid * 2;
            oh[0] = hp[0]; oh[1] = hp[1];
            ol[0] = lp[0]; ol[1] = lp[1];
            float s = f[0]*f[0] + f[1]*f[1] + f[2]*f[2] + f[3]*f[3];
#pragma unroll
            for (int o = 16; o > 0; o >>= 1) s += __shfl_xor_sync(0xFFFFFFFFu, s, o);
            if (lid == 0) g_tsq[row] = s;
        }
        return;
    }

    // ---- new_state part: 16 batches per block (more blocks -> higher occupancy)
    __shared__ float s_s[16][128];
    __shared__ float s_p[16][16];
    const int m  = blockIdx.y;
    const int b0 = blockIdx.x * 16;
    const int h  = threadIdx.x;

    for (int i = h; i < 16 * 128; i += 128) s_s[i >> 7][i & 127] = state[b0 * 128 + i];
    for (int i = h; i < 16 * 16;  i += 128) s_p[i >> 4][i & 15]  = phi[b0 * 16 + i];
    __syncthreads();

    float acc[16];
#pragma unroll
    for (int bb = 0; bb < 16; bb++) acc[bb] = 0.0f;

    const float* Am = A + (size_t)m * D_ * D_ + h;
#pragma unroll 4
    for (int d0 = 0; d0 < 128; d0 += 4) {
        float a0 = Am[(d0 + 0) * 128], a1 = Am[(d0 + 1) * 128];
        float a2 = Am[(d0 + 2) * 128], a3 = Am[(d0 + 3) * 128];
#pragma unroll
        for (int bb = 0; bb < 16; bb++) {
            float4 sv = *reinterpret_cast<const float4*>(&s_s[bb][d0]);
            acc[bb] = fmaf(sv.x, a0, acc[bb]);
            acc[bb] = fmaf(sv.y, a1, acc[bb]);
            acc[bb] = fmaf(sv.z, a2, acc[bb]);
            acc[bb] = fmaf(sv.w, a3, acc[bb]);
        }
    }
    const float* Bm = Bin + (size_t)m * P_ * D_ + h;
#pragma unroll
    for (int p0 = 0; p0 < 16; p0 += 4) {
        float a0 = Bm[(p0 + 0) * 128], a1 = Bm[(p0 + 1) * 128];
        float a2 = Bm[(p0 + 2) * 128], a3 = Bm[(p0 + 3) * 128];
#pragma unroll
        for (int bb = 0; bb < 16; bb++) {
            float4 sv = *reinterpret_cast<const float4*>(&s_p[bb][p0]);
            acc[bb] = fmaf(sv.x, a0, acc[bb]);
            acc[bb] = fmaf(sv.y, a1, acc[bb]);
            acc[bb] = fmaf(sv.z, a2, acc[bb]);
            acc[bb] = fmaf(sv.w, a3, acc[bb]);
        }
    }

    __syncthreads();          // done reading s_s; reuse for v^2
#pragma unroll 4
    for (int bb = 0; bb < 16; bb++) {
        float v = tanhf(acc[bb]);
        int r = (b0 + bb) * M_ + m;
        __nv_bfloat16 hi = __float2bfloat16_rn(v);
        float lo = v - __bfloat162float(hi);
        g_nsh[(size_t)r * D_ + h] = hi;
        g_nsl[(size_t)r * D_ + h] = __float2bfloat16_rn(lo);
        if (tail) tail[(size_t)r * D_ + h] = v;
        s_s[bb][h] = v * v;
    }
    __syncthreads();
    if (h < 16) {
        const float4* row = reinterpret_cast<const float4*>(s_s[h]);
        float s = 0.0f;
#pragma unroll
        for (int k = 0; k < 32; k++) { float4 v = row[k]; s += v.x + v.y + v.z + v.w; }
        g_ssq[(b0 + h) * M_ + m] = s;
    }
}

// ---------------------------------------------------------------------------
// Kernel 2: HMMA (bf16 hi/lo x3) GEMM + fused RBF epilogue.
// CTA 128x128, 8 warps, warp tile 64x32.
// 2-stage cp.async pipeline over k-chunks of 32 (4 chunks).
// Stage = 4 tiles (Ah, Al, Bh, Bl) x (128 rows x 64B) = 32KB; 2 stages + norms
// = 66.5KB -> 3 CTAs/SM.
// Swizzle: slot = c ^ (r&3) ^ (((r>>2)&1)<<1), conflict-free for ldmatrix.
// ---------------------------------------------------------------------------
#define STG_STRIDE 32768
#define TILE_STRIDE 8192
#define OFF_SSQ  65536
#define OFF_TSQ  66048
#define SMEM_BYTES 66560

__global__ __launch_bounds__(256, 3) void sim_mma_kernel(float* __restrict__ out)
{
    extern __shared__ __align__(1024) char smem[];
    const uint32_t sb = smem_u32(smem);
    const int tid = threadIdx.x;
    const int wid = tid >> 5;
    const int lid = tid & 31;
    const int warp_m = (wid >> 2) * 64;
    const int warp_n = (wid & 3) * 32;
    const int r0 = blockIdx.y * TMT;
    const int t0 = blockIdx.x * TNT;

    const __nv_bfloat16* srcs[4] = {
        g_nsh + (size_t)r0 * D_, g_nsl + (size_t)r0 * D_,
        g_tjh + (size_t)t0 * D_, g_tjl + (size_t)t0 * D_ };

    // fill one stage (k-chunk st -> slot st&1): 8 x 16B per thread
    auto fill = [&](int st) {
        const uint32_t sbase = sb + (uint32_t)(st & 1) * STG_STRIDE;
#pragma unroll
        for (int t = 0; t < 8; t++) {
            const int tile = t >> 1;
            const int rem  = ((t & 1) << 8) + tid;     // 0..511
            const int r = rem >> 2, c = rem & 3;
            const uint32_t slot = (uint32_t)(c ^ (r & 3) ^ (((r >> 2) & 1) << 1));
            const uint32_t dst = sbase + (uint32_t)tile * TILE_STRIDE
                               + (uint32_t)r * 64u + (slot << 4);
            cpasync16(dst, srcs[tile] + r * D_ + st * 32 + c * 8);
        }
    };

    // norms into smem (regular loads, before pipeline)
    if (tid < 128) reinterpret_cast<float*>(smem + OFF_SSQ)[tid] = g_ssq[r0 + tid];
    else           reinterpret_cast<float*>(smem + OFF_TSQ)[tid - 128] = g_tsq[t0 + tid - 128];

    fill(0); CP_COMMIT();
    fill(1); CP_COMMIT();

    float d[4][4][4];
#pragma unroll
    for (int a = 0; a < 4; a++)
#pragma unroll
        for (int b = 0; b < 4; b++)
#pragma unroll
            for (int c = 0; c < 4; c++) d[a][b][c] = 0.0f;

    // per-lane ldmatrix row addressing
    uint32_t rowOffA[4], rowOffB[2];
    uint32_t rxA, rxB;
    {
        const int ra = warp_m + (lid & 15);     // + mt*16
        rxA = (uint32_t)((ra & 3) ^ (((ra >> 2) & 1) << 1));
#pragma unroll
        for (int mt = 0; mt < 4; mt++) rowOffA[mt] = (uint32_t)(ra + mt * 16) * 64u;
        const int rb = warp_n + ((lid & 16) >> 1) + (lid & 7);   // + np*16
        rxB = (uint32_t)((rb & 3) ^ (((rb >> 2) & 1) << 1));
#pragma unroll
        for (int np = 0; np < 2; np++) rowOffB[np] = (uint32_t)(rb + np * 16) * 64u;
    }
    const uint32_t aSel = (lid >> 4) & 1;   // 16B half within 32B k-step
    const uint32_t bSel = (lid >> 3) & 1;

#pragma unroll
    for (int st = 0; st < 4; st++) {
        CP_WAIT(1);
        __syncthreads();
        const uint32_t sbs = sb + (uint32_t)(st & 1) * STG_STRIDE;

#pragma unroll
        for (int ks = 0; ks < 2; ks++) {
            const uint32_t cA = (uint32_t)(ks * 2) + aSel;
            const uint32_t cB = (uint32_t)(ks * 2) + bSel;
            uint32_t bqh[2][4], bql[2][4];
#pragma unroll
            for (int np = 0; np < 2; np++) {
                const uint32_t bo = sbs + 2u * TILE_STRIDE + rowOffB[np] + (((cB ^ rxB)) << 4);
                ldsm4(bqh[np], bo);
                ldsm4(bql[np], bo + TILE_STRIDE);
            }
#pragma unroll
            for (int mt = 0; mt < 4; mt++) {
                uint32_t ah[4], al[4];
                const uint32_t ao = sbs + rowOffA[mt] + (((cA ^ rxA)) << 4);
                ldsm4(ah, ao);
                ldsm4(al, ao + TILE_STRIDE);
#pragma unroll
                for (int nt = 0; nt < 4; nt++) {
                    const uint32_t* bh = &bqh[nt >> 1][(nt & 1) * 2];
                    const uint32_t* bl = &bql[nt >> 1][(nt & 1) * 2];
                    mma_bf16(d[mt][nt], ah, bh);
                    mma_bf16(d[mt][nt], ah, bl);
                    mma_bf16(d[mt][nt], al, bh);
                }
            }
        }
        __syncthreads();        // all reads of slot st&1 done before refill
        if (st + 2 < 4) fill(st + 2);
        CP_COMMIT();            // real or empty, keeps group count aligned
    }

    // ---- fused RBF epilogue from accumulator registers
    const float* s_ssq = reinterpret_cast<const float*>(smem + OFF_SSQ);
    const float* s_tsq = reinterpret_cast<const float*>(smem + OFF_TSQ);
    const float NL2E = -1.4426950408889634f;
    const float SC64 = 5.421010862427522e-20f;   // 2^-64

#pragma unroll
    for (int mt = 0; mt < 4; mt++) {
        const int lr = warp_m + mt * 16 + (lid >> 2);
        const float sq0 = s_ssq[lr];
        const float sq1 = s_ssq[lr + 8];
        float* row0 = out + (size_t)(r0 + lr) * T_ + t0;
        float* row1 = row0 + (size_t)8 * T_;
#pragma unroll
        for (int nt = 0; nt < 4; nt++) {
            const int lc = warp_n + nt * 8 + (lid & 3) * 2;
            const float tq0 = s_tsq[lc], tq1 = s_tsq[lc + 1];
            float in[4] = { sq0 + tq0, sq0 + tq1, sq1 + tq0, sq1 + tq1 };
            float o[4];
#pragma unroll
            for (int j = 0; j < 4; j++) {
                float dd = fmaf(-2.0f, d[mt][nt][j], in[j]);
                dd = fmaxf(dd, 0.0f);
                float t = NL2E * dd;
                float tb = t, sc = 1.0f;
                if (t < -80.0f) { tb = t + 64.0f; sc = SC64; }
                o[j] = ex2a(tb) * sc;
            }
            *reinterpret_cast<float2*>(row0 + lc) = make_float2(o[0], o[1]);
            *reinterpret_cast<float2*>(row1 + lc) = make_float2(o[2], o[3]);
        }
    }
}

// ---------------------------------------------------------------------------
extern "C" void kernel_launch(void* const* d_in, const int* in_sizes, int n_in,
                              void* d_out, int out_size) {
    const float *phi = nullptr, *state = nullptr, *traj = nullptr, *A = nullptr, *Bin = nullptr;
    for (int i = 0; i < n_in; i++) {
        switch (in_sizes[i]) {
            case B_ * P_:      phi   = (const float*)d_in[i]; break;  // 8192
            case B_ * D_:      state = (const float*)d_in[i]; break;  // 65536
            case T_ * D_:      traj  = (const float*)d_in[i]; break;  // 524288
            case M_ * D_ * D_: A     = (const float*)d_in[i]; break;  // 262144
            case M_ * P_ * D_: Bin   = (const float*)d_in[i]; break;  // 32768
        }
    }
    float* out = (float*)d_out;
    const long long SIMSZ = (long long)R_ * T_;
    const long long NSSZ  = (long long)R_ * D_;
    float* tail = ((long long)out_size >= SIMSZ + NSSZ) ? out + SIMSZ : nullptr;

    prep_kernel<<<dim3(48, 16), 128>>>(phi, state, A, Bin, traj, tail);

    cudaFuncSetAttribute(sim_mma_kernel, cudaFuncAttributeMaxDynamicSharedMemorySize, SMEM_BYTES);
    sim_mma_kernel<<<dim3(T_ / TNT, R_ / TMT), 256, SMEM_BYTES>>>(out);
}

// round 6
// speedup vs baseline: 1.9919x; 1.9919x over previous
#include <cuda_runtime.h>
#include <cuda_bf16.h>
#include <cstdint>

#define B_  512
#define M_  16
#define D_  128
#define P_  16
#define T_  4096
#define R_  (B_*M_)          // 8192 rows
#define TMT 128              // CTA tile rows
#define TNT 128              // CTA tile cols

// ---- device-global scratch (no allocations allowed) ----
__device__ __nv_bfloat16 g_nsh[R_ * D_];
__device__ __nv_bfloat16 g_nsl[R_ * D_];
__device__ __nv_bfloat16 g_tjh[T_ * D_];
__device__ __nv_bfloat16 g_tjl[T_ * D_];
__device__ float g_ssq[R_];
__device__ float g_tsq[T_];

// ---------------------------------------------------------------- helpers
__device__ __forceinline__ uint32_t smem_u32(const void* p) {
    uint32_t a;
    asm("{ .reg .u64 t; cvta.to.shared.u64 t, %1; cvt.u32.u64 %0, t; }" : "=r"(a) : "l"(p));
    return a;
}
__device__ __forceinline__ float ex2a(float x) {
    float r; asm("ex2.approx.f32 %0, %1;" : "=f"(r) : "f"(x)); return r;
}
__device__ __forceinline__ void cpasync16(uint32_t s, const void* g) {
    asm volatile("cp.async.cg.shared.global [%0], [%1], 16;" :: "r"(s), "l"(g));
}
#define CP_COMMIT() asm volatile("cp.async.commit_group;" ::: "memory")
#define CP_WAIT(n)  asm volatile("cp.async.wait_group %0;" :: "n"(n) : "memory")

__device__ __forceinline__ void ldsm4(uint32_t* r, uint32_t a) {
    asm volatile("ldmatrix.sync.aligned.m8n8.x4.shared.b16 {%0,%1,%2,%3}, [%4];"
        : "=r"(r[0]), "=r"(r[1]), "=r"(r[2]), "=r"(r[3]) : "r"(a));
}
__device__ __forceinline__ void mma_bf16(float* d, const uint32_t* a, const uint32_t* b) {
    asm volatile(
        "mma.sync.aligned.m16n8k16.row.col.f32.bf16.bf16.f32 "
        "{%0,%1,%2,%3}, {%4,%5,%6,%7}, {%8,%9}, {%0,%1,%2,%3};"
        : "+f"(d[0]), "+f"(d[1]), "+f"(d[2]), "+f"(d[3])
        : "r"(a[0]), "r"(a[1]), "r"(a[2]), "r"(a[3]), "r"(b[0]), "r"(b[1]));
}

// ---------------------------------------------------------------------------
// Kernel 1 (fused): blockIdx.x < 32  -> new_state (16 batches/block) + split + ssq
//                   blockIdx.x >= 32 -> trajectory hi/lo split + tsq
// grid dim3(48, 16), 128 threads.
// ---------------------------------------------------------------------------
__global__ __launch_bounds__(128) void prep_kernel(
    const float* __restrict__ phi, const float* __restrict__ state,
    const float* __restrict__ A,   const float* __restrict__ Bin,
    const float* __restrict__ tj,  float* __restrict__ tail)
{
    if (blockIdx.x >= 32) {
        // ---- trajectory part: 256 logical blocks, 16 rows each, 4 warps
        const int blk = blockIdx.y * 16 + (blockIdx.x - 32);
        const int wrp = threadIdx.x >> 5;
        const int lid = threadIdx.x & 31;
#pragma unroll
        for (int rr = 0; rr < 4; rr++) {
            const int row = blk * 16 + wrp * 4 + rr;
            float4 v = reinterpret_cast<const float4*>(tj)[row * 32 + lid];
            float f[4] = {v.x, v.y, v.z, v.w};
            uint32_t hp[2], lp[2];
#pragma unroll
            for (int j = 0; j < 2; j++) {
                __nv_bfloat16 h0 = __float2bfloat16_rn(f[2 * j]);
                __nv_bfloat16 h1 = __float2bfloat16_rn(f[2 * j + 1]);
                __nv_bfloat16 l0 = __float2bfloat16_rn(f[2 * j] - __bfloat162float(h0));
                __nv_bfloat16 l1 = __float2bfloat16_rn(f[2 * j + 1] - __bfloat162float(h1));
                hp[j] = (uint32_t)__bfloat16_as_ushort(h0) | ((uint32_t)__bfloat16_as_ushort(h1) << 16);
                lp[j] = (uint32_t)__bfloat16_as_ushort(l0) | ((uint32_t)__bfloat16_as_ushort(l1) << 16);
            }
            uint32_t* oh = reinterpret_cast<uint32_t*>(g_tjh) + row * 64 + lid * 2;
            uint32_t* ol = reinterpret_cast<uint32_t*>(g_tjl) + row * 64 + lid * 2;
            oh[0] = hp[0]; oh[1] = hp[1];
            ol[0] = lp[0]; ol[1] = lp[1];
            float s = f[0]*f[0] + f[1]*f[1] + f[2]*f[2] + f[3]*f[3];
#pragma unroll
            for (int o = 16; o > 0; o >>= 1) s += __shfl_xor_sync(0xFFFFFFFFu, s, o);
            if (lid == 0) g_tsq[row] = s;
        }
        return;
    }

    // ---- new_state part: 16 batches per block
    __shared__ float s_s[16][128];
    __shared__ float s_p[16][16];
    const int m  = blockIdx.y;
    const int b0 = blockIdx.x * 16;
    const int h  = threadIdx.x;

    for (int i = h; i < 16 * 128; i += 128) s_s[i >> 7][i & 127] = state[b0 * 128 + i];
    for (int i = h; i < 16 * 16;  i += 128) s_p[i >> 4][i & 15]  = phi[b0 * 16 + i];
    __syncthreads();

    float acc[16];
#pragma unroll
    for (int bb = 0; bb < 16; bb++) acc[bb] = 0.0f;

    const float* Am = A + (size_t)m * D_ * D_ + h;
#pragma unroll 4
    for (int d0 = 0; d0 < 128; d0 += 4) {
        float a0 = Am[(d0 + 0) * 128], a1 = Am[(d0 + 1) * 128];
        float a2 = Am[(d0 + 2) * 128], a3 = Am[(d0 + 3) * 128];
#pragma unroll
        for (int bb = 0; bb < 16; bb++) {
            float4 sv = *reinterpret_cast<const float4*>(&s_s[bb][d0]);
            acc[bb] = fmaf(sv.x, a0, acc[bb]);
            acc[bb] = fmaf(sv.y, a1, acc[bb]);
            acc[bb] = fmaf(sv.z, a2, acc[bb]);
            acc[bb] = fmaf(sv.w, a3, acc[bb]);
        }
    }
    const float* Bm = Bin + (size_t)m * P_ * D_ + h;
#pragma unroll
    for (int p0 = 0; p0 < 16; p0 += 4) {
        float a0 = Bm[(p0 + 0) * 128], a1 = Bm[(p0 + 1) * 128];
        float a2 = Bm[(p0 + 2) * 128], a3 = Bm[(p0 + 3) * 128];
#pragma unroll
        for (int bb = 0; bb < 16; bb++) {
            float4 sv = *reinterpret_cast<const float4*>(&s_p[bb][p0]);
            acc[bb] = fmaf(sv.x, a0, acc[bb]);
            acc[bb] = fmaf(sv.y, a1, acc[bb]);
            acc[bb] = fmaf(sv.z, a2, acc[bb]);
            acc[bb] = fmaf(sv.w, a3, acc[bb]);
        }
    }

    __syncthreads();          // done reading s_s; reuse for v^2
#pragma unroll 4
    for (int bb = 0; bb < 16; bb++) {
        float v = tanhf(acc[bb]);
        int r = (b0 + bb) * M_ + m;
        __nv_bfloat16 hi = __float2bfloat16_rn(v);
        float lo = v - __bfloat162float(hi);
        g_nsh[(size_t)r * D_ + h] = hi;
        g_nsl[(size_t)r * D_ + h] = __float2bfloat16_rn(lo);
        if (tail) tail[(size_t)r * D_ + h] = v;
        s_s[bb][h] = v * v;
    }
    __syncthreads();
    if (h < 16) {
        const float4* row = reinterpret_cast<const float4*>(s_s[h]);
        float s = 0.0f;
#pragma unroll
        for (int k = 0; k < 32; k++) { float4 v = row[k]; s += v.x + v.y + v.z + v.w; }
        g_ssq[(b0 + h) * M_ + m] = s;
    }
}

// ---------------------------------------------------------------------------
// Kernel 2: HMMA (bf16 hi/lo x3) GEMM + fused RBF epilogue.
// CTA 128x128, 8 warps, warp tile 64x32, regs capped at 128 (minblocks=2).
// 3-stage cp.async pipeline, SINGLE sync per stage, fill-before-compute:
//   st: wait(1) -> sync -> fill(st+2) -> compute(st)
// Stage = 4 tiles x 8KB = 32KB, slots = st%3, 96KB + norms.
// Swizzle: slot = c ^ (r&3) ^ (((r>>2)&1)<<1), conflict-free for ldmatrix.
// ---------------------------------------------------------------------------
#define STG_STRIDE 32768
#define TILE_STRIDE 8192
#define OFF_SSQ  98304
#define OFF_TSQ  98816
#define SMEM_BYTES 99328

__global__ __launch_bounds__(256, 2) void sim_mma_kernel(float* __restrict__ out)
{
    extern __shared__ __align__(1024) char smem[];
    const uint32_t sb = smem_u32(smem);
    const int tid = threadIdx.x;
    const int wid = tid >> 5;
    const int lid = tid & 31;
    const int warp_m = (wid >> 2) * 64;
    const int warp_n = (wid & 3) * 32;
    const int r0 = blockIdx.y * TMT;
    const int t0 = blockIdx.x * TNT;

    const __nv_bfloat16* srcs[4] = {
        g_nsh + (size_t)r0 * D_, g_nsl + (size_t)r0 * D_,
        g_tjh + (size_t)t0 * D_, g_tjl + (size_t)t0 * D_ };

    // fill one stage (k-chunk st -> slot st%3): 8 x 16B per thread
    auto fill = [&](int st) {
        const uint32_t sbase = sb + (uint32_t)(st % 3) * STG_STRIDE;
#pragma unroll
        for (int t = 0; t < 8; t++) {
            const int tile = t >> 1;
            const int rem  = ((t & 1) << 8) + tid;     // 0..511
            const int r = rem >> 2, c = rem & 3;
            const uint32_t slot = (uint32_t)(c ^ (r & 3) ^ (((r >> 2) & 1) << 1));
            const uint32_t dst = sbase + (uint32_t)tile * TILE_STRIDE
                               + (uint32_t)r * 64u + (slot << 4);
            cpasync16(dst, srcs[tile] + r * D_ + st * 32 + c * 8);
        }
    };

    // norms into smem (regular loads, before pipeline)
    if (tid < 128) reinterpret_cast<float*>(smem + OFF_SSQ)[tid] = g_ssq[r0 + tid];
    else           reinterpret_cast<float*>(smem + OFF_TSQ)[tid - 128] = g_tsq[t0 + tid - 128];

    fill(0); CP_COMMIT();
    fill(1); CP_COMMIT();

    float d[4][4][4];
#pragma unroll
    for (int a = 0; a < 4; a++)
#pragma unroll
        for (int b = 0; b < 4; b++)
#pragma unroll
            for (int c = 0; c < 4; c++) d[a][b][c] = 0.0f;

    // per-lane ldmatrix row addressing
    uint32_t rowOffA[4], rowOffB[2];
    uint32_t rxA, rxB;
    {
        const int ra = warp_m + (lid & 15);     // + mt*16
        rxA = (uint32_t)((ra & 3) ^ (((ra >> 2) & 1) << 1));
#pragma unroll
        for (int mt = 0; mt < 4; mt++) rowOffA[mt] = (uint32_t)(ra + mt * 16) * 64u;
        const int rb = warp_n + ((lid & 16) >> 1) + (lid & 7);   // + np*16
        rxB = (uint32_t)((rb & 3) ^ (((rb >> 2) & 1) << 1));
#pragma unroll
        for (int np = 0; np < 2; np++) rowOffB[np] = (uint32_t)(rb + np * 16) * 64u;
    }
    const uint32_t aSel = (lid >> 4) & 1;   // 16B half within 32B k-step
    const uint32_t bSel = (lid >> 3) & 1;

#pragma unroll
    for (int st = 0; st < 4; st++) {
        if (st < 3) { CP_WAIT(1); } else { CP_WAIT(0); }
        __syncthreads();
        // issue next chunk's loads BEFORE compute so they overlap with MMAs.
        // slot (st+2)%3 == (st-1)%3, whose compute finished before the sync above.
        if (st + 2 < 4) { fill(st + 2); CP_COMMIT(); }

        const uint32_t sbs = sb + (uint32_t)(st % 3) * STG_STRIDE;
#pragma unroll
        for (int ks = 0; ks < 2; ks++) {
            const uint32_t cA = (uint32_t)(ks * 2) + aSel;
            const uint32_t cB = (uint32_t)(ks * 2) + bSel;
            uint32_t bqh[2][4], bql[2][4];
#pragma unroll
            for (int np = 0; np < 2; np++) {
                const uint32_t bo = sbs + 2u * TILE_STRIDE + rowOffB[np] + (((cB ^ rxB)) << 4);
                ldsm4(bqh[np], bo);
                ldsm4(bql[np], bo + TILE_STRIDE);
            }
#pragma unroll
            for (int mt = 0; mt < 4; mt++) {
                uint32_t ah[4], al[4];
                const uint32_t ao = sbs + rowOffA[mt] + (((cA ^ rxA)) << 4);
                ldsm4(ah, ao);
                ldsm4(al, ao + TILE_STRIDE);
#pragma unroll
                for (int nt = 0; nt < 4; nt++) {
                    const uint32_t* bh = &bqh[nt >> 1][(nt & 1) * 2];
                    const uint32_t* bl = &bql[nt >> 1][(nt & 1) * 2];
                    mma_bf16(d[mt][nt], ah, bh);
                    mma_bf16(d[mt][nt], ah, bl);
                    mma_bf16(d[mt][nt], al, bh);
                }
            }
        }
    }

    // ---- fused RBF epilogue from accumulator registers
    const float* s_ssq = reinterpret_cast<const float*>(smem + OFF_SSQ);
    const float* s_tsq = reinterpret_cast<const float*>(smem + OFF_TSQ);
    const float NL2E = -1.4426950408889634f;
    const float SC64 = 5.421010862427522e-20f;   // 2^-64

#pragma unroll
    for (int mt = 0; mt < 4; mt++) {
        const int lr = warp_m + mt * 16 + (lid >> 2);
        const float sq0 = s_ssq[lr];
        const float sq1 = s_ssq[lr + 8];
        float* row0 = out + (size_t)(r0 + lr) * T_ + t0;
        float* row1 = row0 + (size_t)8 * T_;
#pragma unroll
        for (int nt = 0; nt < 4; nt++) {
            const int lc = warp_n + nt * 8 + (lid & 3) * 2;
            const float tq0 = s_tsq[lc], tq1 = s_tsq[lc + 1];
            float in[4] = { sq0 + tq0, sq0 + tq1, sq1 + tq0, sq1 + tq1 };
            float o[4];
#pragma unroll
            for (int j = 0; j < 4; j++) {
                float dd = fmaf(-2.0f, d[mt][nt][j], in[j]);
                dd = fmaxf(dd, 0.0f);
                float t = NL2E * dd;
                float tb = t, sc = 1.0f;
                if (t < -80.0f) { tb = t + 64.0f; sc = SC64; }
                o[j] = ex2a(tb) * sc;
            }
            *reinterpret_cast<float2*>(row0 + lc) = make_float2(o[0], o[1]);
            *reinterpret_cast<float2*>(row1 + lc) = make_float2(o[2], o[3]);
        }
    }
}

// ---------------------------------------------------------------------------
extern "C" void kernel_launch(void* const* d_in, const int* in_sizes, int n_in,
                              void* d_out, int out_size) {
    const float *phi = nullptr, *state = nullptr, *traj = nullptr, *A = nullptr, *Bin = nullptr;
    for (int i = 0; i < n_in; i++) {
        switch (in_sizes[i]) {
            case B_ * P_:      phi   = (const float*)d_in[i]; break;  // 8192
            case B_ * D_:      state = (const float*)d_in[i]; break;  // 65536
            case T_ * D_:      traj  = (const float*)d_in[i]; break;  // 524288
            case M_ * D_ * D_: A     = (const float*)d_in[i]; break;  // 262144
            case M_ * P_ * D_: Bin   = (const float*)d_in[i]; break;  // 32768
        }
    }
    float* out = (float*)d_out;
    const long long SIMSZ = (long long)R_ * T_;
    const long long NSSZ  = (long long)R_ * D_;
    float* tail = ((long long)out_size >= SIMSZ + NSSZ) ? out + SIMSZ : nullptr;

    prep_kernel<<<dim3(48, 16), 128>>>(phi, state, A, Bin, traj, tail);

    cudaFuncSetAttribute(sim_mma_kernel, cudaFuncAttributeMaxDynamicSharedMemorySize, SMEM_BYTES);
    sim_mma_kernel<<<dim3(T_ / TNT, R_ / TMT), 256, SMEM_BYTES>>>(out);
}

// round 7
// speedup vs baseline: 1.9988x; 1.0035x over previous
#include <cuda_runtime.h>
#include <cuda_bf16.h>
#include <cstdint>

#define B_  512
#define M_  16
#define D_  128
#define P_  16
#define T_  4096
#define R_  (B_*M_)          // 8192 rows
#define TMT 128              // CTA tile rows
#define TNT 128              // CTA tile cols

// ---- device-global scratch (no allocations allowed) ----
__device__ __nv_bfloat16 g_nsh[R_ * D_];
__device__ __nv_bfloat16 g_nsl[R_ * D_];
__device__ __nv_bfloat16 g_tjh[T_ * D_];
__device__ __nv_bfloat16 g_tjl[T_ * D_];
__device__ float g_ssq[R_];
__device__ float g_tsq[T_];

// ---------------------------------------------------------------- helpers
__device__ __forceinline__ uint32_t smem_u32(const void* p) {
    uint32_t a;
    asm("{ .reg .u64 t; cvta.to.shared.u64 t, %1; cvt.u32.u64 %0, t; }" : "=r"(a) : "l"(p));
    return a;
}
__device__ __forceinline__ float ex2a(float x) {
    float r; asm("ex2.approx.f32 %0, %1;" : "=f"(r) : "f"(x)); return r;
}
__device__ __forceinline__ float rcpa(float x) {
    float r; asm("rcp.approx.f32 %0, %1;" : "=f"(r) : "f"(x)); return r;
}
// tanh(x) = 1 - 2/(e^{2x}+1); ~1e-6 abs err via ex2/rcp approx (vs slow tanhf)
__device__ __forceinline__ float fast_tanh(float x) {
    const float TWO_L2E = 2.8853900817779268f;   // 2*log2(e)
    float e = ex2a(x * TWO_L2E);
    return fmaf(-2.0f, rcpa(e + 1.0f), 1.0f);
}
__device__ __forceinline__ void cpasync16(uint32_t s, const void* g) {
    asm volatile("cp.async.cg.shared.global [%0], [%1], 16;" :: "r"(s), "l"(g));
}
#define CP_COMMIT() asm volatile("cp.async.commit_group;" ::: "memory")
#define CP_WAIT(n)  asm volatile("cp.async.wait_group %0;" :: "n"(n) : "memory")

__device__ __forceinline__ void ldsm4(uint32_t* r, uint32_t a) {
    asm volatile("ldmatrix.sync.aligned.m8n8.x4.shared.b16 {%0,%1,%2,%3}, [%4];"
        : "=r"(r[0]), "=r"(r[1]), "=r"(r[2]), "=r"(r[3]) : "r"(a));
}
__device__ __forceinline__ void mma_bf16(float* d, const uint32_t* a, const uint32_t* b) {
    asm volatile(
        "mma.sync.aligned.m16n8k16.row.col.f32.bf16.bf16.f32 "
        "{%0,%1,%2,%3}, {%4,%5,%6,%7}, {%8,%9}, {%0,%1,%2,%3};"
        : "+f"(d[0]), "+f"(d[1]), "+f"(d[2]), "+f"(d[3])
        : "r"(a[0]), "r"(a[1]), "r"(a[2]), "r"(a[3]), "r"(b[0]), "r"(b[1]));
}

// ---------------------------------------------------------------------------
// Kernel 1 (fused): blockIdx.x < 32  -> new_state (16 batches/block) + split + ssq
//                   blockIdx.x >= 32 -> trajectory hi/lo split + tsq
// grid dim3(48, 16), 128 threads.
// ---------------------------------------------------------------------------
__global__ __launch_bounds__(128) void prep_kernel(
    const float* __restrict__ phi, const float* __restrict__ state,
    const float* __restrict__ A,   const float* __restrict__ Bin,
    const float* __restrict__ tj,  float* __restrict__ tail)
{
    if (blockIdx.x >= 32) {
        // ---- trajectory part: 256 logical blocks, 16 rows each, 4 warps
        const int blk = blockIdx.y * 16 + (blockIdx.x - 32);
        const int wrp = threadIdx.x >> 5;
        const int lid = threadIdx.x & 31;
#pragma unroll
        for (int rr = 0; rr < 4; rr++) {
            const int row = blk * 16 + wrp * 4 + rr;
            float4 v = reinterpret_cast<const float4*>(tj)[row * 32 + lid];
            float f[4] = {v.x, v.y, v.z, v.w};
            uint32_t hp[2], lp[2];
#pragma unroll
            for (int j = 0; j < 2; j++) {
                __nv_bfloat16 h0 = __float2bfloat16_rn(f[2 * j]);
                __nv_bfloat16 h1 = __float2bfloat16_rn(f[2 * j + 1]);
                __nv_bfloat16 l0 = __float2bfloat16_rn(f[2 * j] - __bfloat162float(h0));
                __nv_bfloat16 l1 = __float2bfloat16_rn(f[2 * j + 1] - __bfloat162float(h1));
                hp[j] = (uint32_t)__bfloat16_as_ushort(h0) | ((uint32_t)__bfloat16_as_ushort(h1) << 16);
                lp[j] = (uint32_t)__bfloat16_as_ushort(l0) | ((uint32_t)__bfloat16_as_ushort(l1) << 16);
            }
            uint32_t* oh = reinterpret_cast<uint32_t*>(g_tjh) + row * 64 + lid * 2;
            uint32_t* ol = reinterpret_cast<uint32_t*>(g_tjl) + row * 64 + lid * 2;
            oh[0] = hp[0]; oh[1] = hp[1];
            ol[0] = lp[0]; ol[1] = lp[1];
            float s = f[0]*f[0] + f[1]*f[1] + f[2]*f[2] + f[3]*f[3];
#pragma unroll
            for (int o = 16; o > 0; o >>= 1) s += __shfl_xor_sync(0xFFFFFFFFu, s, o);
            if (lid == 0) g_tsq[row] = s;
        }
        return;
    }

    // ---- new_state part: 16 batches per block
    __shared__ float s_s[16][128];
    __shared__ float s_p[16][16];
    const int m  = blockIdx.y;
    const int b0 = blockIdx.x * 16;
    const int h  = threadIdx.x;

    for (int i = h; i < 16 * 128; i += 128) s_s[i >> 7][i & 127] = state[b0 * 128 + i];
    for (int i = h; i < 16 * 16;  i += 128) s_p[i >> 4][i & 15]  = phi[b0 * 16 + i];
    __syncthreads();

    float acc[16];
#pragma unroll
    for (int bb = 0; bb < 16; bb++) acc[bb] = 0.0f;

    const float* Am = A + (size_t)m * D_ * D_ + h;
#pragma unroll 4
    for (int d0 = 0; d0 < 128; d0 += 4) {
        float a0 = Am[(d0 + 0) * 128], a1 = Am[(d0 + 1) * 128];
        float a2 = Am[(d0 + 2) * 128], a3 = Am[(d0 + 3) * 128];
#pragma unroll
        for (int bb = 0; bb < 16; bb++) {
            float4 sv = *reinterpret_cast<const float4*>(&s_s[bb][d0]);
            acc[bb] = fmaf(sv.x, a0, acc[bb]);
            acc[bb] = fmaf(sv.y, a1, acc[bb]);
            acc[bb] = fmaf(sv.z, a2, acc[bb]);
            acc[bb] = fmaf(sv.w, a3, acc[bb]);
        }
    }
    const float* Bm = Bin + (size_t)m * P_ * D_ + h;
#pragma unroll
    for (int p0 = 0; p0 < 16; p0 += 4) {
        float a0 = Bm[(p0 + 0) * 128], a1 = Bm[(p0 + 1) * 128];
        float a2 = Bm[(p0 + 2) * 128], a3 = Bm[(p0 + 3) * 128];
#pragma unroll
        for (int bb = 0; bb < 16; bb++) {
            float4 sv = *reinterpret_cast<const float4*>(&s_p[bb][p0]);
            acc[bb] = fmaf(sv.x, a0, acc[bb]);
            acc[bb] = fmaf(sv.y, a1, acc[bb]);
            acc[bb] = fmaf(sv.z, a2, acc[bb]);
            acc[bb] = fmaf(sv.w, a3, acc[bb]);
        }
    }

    __syncthreads();          // done reading s_s; reuse for v^2
#pragma unroll 4
    for (int bb = 0; bb < 16; bb++) {
        float v = fast_tanh(acc[bb]);
        int r = (b0 + bb) * M_ + m;
        __nv_bfloat16 hi = __float2bfloat16_rn(v);
        float lo = v - __bfloat162float(hi);
        g_nsh[(size_t)r * D_ + h] = hi;
        g_nsl[(size_t)r * D_ + h] = __float2bfloat16_rn(lo);
        if (tail) tail[(size_t)r * D_ + h] = v;
        s_s[bb][h] = v * v;
    }
    __syncthreads();
    if (h < 16) {
        const float4* row = reinterpret_cast<const float4*>(s_s[h]);
        float s = 0.0f;
#pragma unroll
        for (int k = 0; k < 32; k++) { float4 v = row[k]; s += v.x + v.y + v.z + v.w; }
        g_ssq[(b0 + h) * M_ + m] = s;
    }
}

// ---------------------------------------------------------------------------
// Kernel 2: HMMA (bf16 hi/lo x3) GEMM + fused RBF epilogue.
// CTA 128x128, 8 warps, warp tile 64x32, regs capped at 128 (minblocks=2).
// 3-stage cp.async pipeline, SINGLE sync per stage, fill-before-compute.
// (unchanged from round 6: 78.5us, protect it)
// ---------------------------------------------------------------------------
#define STG_STRIDE 32768
#define TILE_STRIDE 8192
#define OFF_SSQ  98304
#define OFF_TSQ  98816
#define SMEM_BYTES 99328

__global__ __launch_bounds__(256, 2) void sim_mma_kernel(float* __restrict__ out)
{
    extern __shared__ __align__(1024) char smem[];
    const uint32_t sb = smem_u32(smem);
    const int tid = threadIdx.x;
    const int wid = tid >> 5;
    const int lid = tid & 31;
    const int warp_m = (wid >> 2) * 64;
    const int warp_n = (wid & 3) * 32;
    const int r0 = blockIdx.y * TMT;
    const int t0 = blockIdx.x * TNT;

    const __nv_bfloat16* srcs[4] = {
        g_nsh + (size_t)r0 * D_, g_nsl + (size_t)r0 * D_,
        g_tjh + (size_t)t0 * D_, g_tjl + (size_t)t0 * D_ };

    auto fill = [&](int st) {
        const uint32_t sbase = sb + (uint32_t)(st % 3) * STG_STRIDE;
#pragma unroll
        for (int t = 0; t < 8; t++) {
            const int tile = t >> 1;
            const int rem  = ((t & 1) << 8) + tid;     // 0..511
            const int r = rem >> 2, c = rem & 3;
            const uint32_t slot = (uint32_t)(c ^ (r & 3) ^ (((r >> 2) & 1) << 1));
            const uint32_t dst = sbase + (uint32_t)tile * TILE_STRIDE
                               + (uint32_t)r * 64u + (slot << 4);
            cpasync16(dst, srcs[tile] + r * D_ + st * 32 + c * 8);
        }
    };

    if (tid < 128) reinterpret_cast<float*>(smem + OFF_SSQ)[tid] = g_ssq[r0 + tid];
    else           reinterpret_cast<float*>(smem + OFF_TSQ)[tid - 128] = g_tsq[t0 + tid - 128];

    fill(0); CP_COMMIT();
    fill(1); CP_COMMIT();

    float d[4][4][4];
#pragma unroll
    for (int a = 0; a < 4; a++)
#pragma unroll
        for (int b = 0; b < 4; b++)
#pragma unroll
            for (int c = 0; c < 4; c++) d[a][b][c] = 0.0f;

    uint32_t rowOffA[4], rowOffB[2];
    uint32_t rxA, rxB;
    {
        const int ra = warp_m + (lid & 15);
        rxA = (uint32_t)((ra & 3) ^ (((ra >> 2) & 1) << 1));
#pragma unroll
        for (int mt = 0; mt < 4; mt++) rowOffA[mt] = (uint32_t)(ra + mt * 16) * 64u;
        const int rb = warp_n + ((lid & 16) >> 1) + (lid & 7);
        rxB = (uint32_t)((rb & 3) ^ (((rb >> 2) & 1) << 1));
#pragma unroll
        for (int np = 0; np < 2; np++) rowOffB[np] = (uint32_t)(rb + np * 16) * 64u;
    }
    const uint32_t aSel = (lid >> 4) & 1;
    const uint32_t bSel = (lid >> 3) & 1;

#pragma unroll
    for (int st = 0; st < 4; st++) {
        if (st < 3) { CP_WAIT(1); } else { CP_WAIT(0); }
        __syncthreads();
        if (st + 2 < 4) { fill(st + 2); CP_COMMIT(); }

        const uint32_t sbs = sb + (uint32_t)(st % 3) * STG_STRIDE;
#pragma unroll
        for (int ks = 0; ks < 2; ks++) {
            const uint32_t cA = (uint32_t)(ks * 2) + aSel;
            const uint32_t cB = (uint32_t)(ks * 2) + bSel;
            uint32_t bqh[2][4], bql[2][4];
#pragma unroll
            for (int np = 0; np < 2; np++) {
                const uint32_t bo = sbs + 2u * TILE_STRIDE + rowOffB[np] + (((cB ^ rxB)) << 4);
                ldsm4(bqh[np], bo);
                ldsm4(bql[np], bo + TILE_STRIDE);
            }
#pragma unroll
            for (int mt = 0; mt < 4; mt++) {
                uint32_t ah[4], al[4];
                const uint32_t ao = sbs + rowOffA[mt] + (((cA ^ rxA)) << 4);
                ldsm4(ah, ao);
                ldsm4(al, ao + TILE_STRIDE);
#pragma unroll
                for (int nt = 0; nt < 4; nt++) {
                    const uint32_t* bh = &bqh[nt >> 1][(nt & 1) * 2];
                    const uint32_t* bl = &bql[nt >> 1][(nt & 1) * 2];
                    mma_bf16(d[mt][nt], ah, bh);
                    mma_bf16(d[mt][nt], ah, bl);
                    mma_bf16(d[mt][nt], al, bh);
                }
            }
        }
    }

    const float* s_ssq = reinterpret_cast<const float*>(smem + OFF_SSQ);
    const float* s_tsq = reinterpret_cast<const float*>(smem + OFF_TSQ);
    const float NL2E = -1.4426950408889634f;
    const float SC64 = 5.421010862427522e-20f;   // 2^-64

#pragma unroll
    for (int mt = 0; mt < 4; mt++) {
        const int lr = warp_m + mt * 16 + (lid >> 2);
        const float sq0 = s_ssq[lr];
        const float sq1 = s_ssq[lr + 8];
        float* row0 = out + (size_t)(r0 + lr) * T_ + t0;
        float* row1 = row0 + (size_t)8 * T_;
#pragma unroll
        for (int nt = 0; nt < 4; nt++) {
            const int lc = warp_n + nt * 8 + (lid & 3) * 2;
            const float tq0 = s_tsq[lc], tq1 = s_tsq[lc + 1];
            float in[4] = { sq0 + tq0, sq0 + tq1, sq1 + tq0, sq1 + tq1 };
            float o[4];
#pragma unroll
            for (int j = 0; j < 4; j++) {
                float dd = fmaf(-2.0f, d[mt][nt][j], in[j]);
                dd = fmaxf(dd, 0.0f);
                float t = NL2E * dd;
                float tb = t, sc = 1.0f;
                if (t < -80.0f) { tb = t + 64.0f; sc = SC64; }
                o[j] = ex2a(tb) * sc;
            }
            *reinterpret_cast<float2*>(row0 + lc) = make_float2(o[0], o[1]);
            *reinterpret_cast<float2*>(row1 + lc) = make_float2(o[2], o[3]);
        }
    }
}

// ---------------------------------------------------------------------------
extern "C" void kernel_launch(void* const* d_in, const int* in_sizes, int n_in,
                              void* d_out, int out_size) {
    const float *phi = nullptr, *state = nullptr, *traj = nullptr, *A = nullptr, *Bin = nullptr;
    for (int i = 0; i < n_in; i++) {
        switch (in_sizes[i]) {
            case B_ * P_:      phi   = (const float*)d_in[i]; break;  // 8192
            case B_ * D_:      state = (const float*)d_in[i]; break;  // 65536
            case T_ * D_:      traj  = (const float*)d_in[i]; break;  // 524288
            case M_ * D_ * D_: A     = (const float*)d_in[i]; break;  // 262144
            case M_ * P_ * D_: Bin   = (const float*)d_in[i]; break;  // 32768
        }
    }
    float* out = (float*)d_out;
    const long long SIMSZ = (long long)R_ * T_;
    const long long NSSZ  = (long long)R_ * D_;
    float* tail = ((long long)out_size >= SIMSZ + NSSZ) ? out + SIMSZ : nullptr;

    prep_kernel<<<dim3(48, 16), 128>>>(phi, state, A, Bin, traj, tail);

    cudaFuncSetAttribute(sim_mma_kernel, cudaFuncAttributeMaxDynamicSharedMemorySize, SMEM_BYTES);
    sim_mma_kernel<<<dim3(T_ / TNT, R_ / TMT), 256, SMEM_BYTES>>>(out);
}

// round 8
// speedup vs baseline: 2.0526x; 1.0269x over previous
#include <cuda_runtime.h>
#include <cuda_bf16.h>
#include <cstdint>

#define B_  512
#define M_  16
#define D_  128
#define P_  16
#define T_  4096
#define R_  (B_*M_)          // 8192 rows
#define TMT 128
#define TNT 128

// ---- device-global scratch (no allocations allowed) ----
__device__ __nv_bfloat16 g_nsh[R_ * D_];
__device__ __nv_bfloat16 g_nsl[R_ * D_];
__device__ __nv_bfloat16 g_tjh[T_ * D_];
__device__ __nv_bfloat16 g_tjl[T_ * D_];
__device__ float g_ssq[R_];
__device__ float g_tsq[T_];

// ---------------------------------------------------------------- helpers
__device__ __forceinline__ uint32_t smem_u32(const void* p) {
    uint32_t a;
    asm("{ .reg .u64 t; cvta.to.shared.u64 t, %1; cvt.u32.u64 %0, t; }" : "=r"(a) : "l"(p));
    return a;
}
__device__ __forceinline__ float ex2a(float x) {
    float r; asm("ex2.approx.f32 %0, %1;" : "=f"(r) : "f"(x)); return r;
}
__device__ __forceinline__ float rcpa(float x) {
    float r; asm("rcp.approx.f32 %0, %1;" : "=f"(r) : "f"(x)); return r;
}
__device__ __forceinline__ float fast_tanh(float x) {
    const float TWO_L2E = 2.8853900817779268f;
    float e = ex2a(x * TWO_L2E);
    return fmaf(-2.0f, rcpa(e + 1.0f), 1.0f);
}
__device__ __forceinline__ void cpasync16(uint32_t s, const void* g) {
    asm volatile("cp.async.cg.shared.global [%0], [%1], 16;" :: "r"(s), "l"(g));
}
#define CP_COMMIT() asm volatile("cp.async.commit_group;" ::: "memory")
#define CP_WAIT(n)  asm volatile("cp.async.wait_group %0;" :: "n"(n) : "memory")

__device__ __forceinline__ void ldsm4(uint32_t* r, uint32_t a) {
    asm volatile("ldmatrix.sync.aligned.m8n8.x4.shared.b16 {%0,%1,%2,%3}, [%4];"
        : "=r"(r[0]), "=r"(r[1]), "=r"(r[2]), "=r"(r[3]) : "r"(a));
}
__device__ __forceinline__ void ldsm4t(uint32_t* r, uint32_t a) {
    asm volatile("ldmatrix.sync.aligned.m8n8.x4.trans.shared.b16 {%0,%1,%2,%3}, [%4];"
        : "=r"(r[0]), "=r"(r[1]), "=r"(r[2]), "=r"(r[3]) : "r"(a));
}
__device__ __forceinline__ void mma_bf16(float* d, const uint32_t* a, const uint32_t* b) {
    asm volatile(
        "mma.sync.aligned.m16n8k16.row.col.f32.bf16.bf16.f32 "
        "{%0,%1,%2,%3}, {%4,%5,%6,%7}, {%8,%9}, {%0,%1,%2,%3};"
        : "+f"(d[0]), "+f"(d[1]), "+f"(d[2]), "+f"(d[3])
        : "r"(a[0]), "r"(a[1]), "r"(a[2]), "r"(a[3]), "r"(b[0]), "r"(b[1]));
}
__device__ __forceinline__ void split4(float4 v, uint32_t& hp0, uint32_t& hp1,
                                       uint32_t& lp0, uint32_t& lp1) {
    __nv_bfloat16 h0 = __float2bfloat16_rn(v.x), h1 = __float2bfloat16_rn(v.y);
    __nv_bfloat16 h2 = __float2bfloat16_rn(v.z), h3 = __float2bfloat16_rn(v.w);
    __nv_bfloat16 l0 = __float2bfloat16_rn(v.x - __bfloat162float(h0));
    __nv_bfloat16 l1 = __float2bfloat16_rn(v.y - __bfloat162float(h1));
    __nv_bfloat16 l2 = __float2bfloat16_rn(v.z - __bfloat162float(h2));
    __nv_bfloat16 l3 = __float2bfloat16_rn(v.w - __bfloat162float(h3));
    hp0 = (uint32_t)__bfloat16_as_ushort(h0) | ((uint32_t)__bfloat16_as_ushort(h1) << 16);
    hp1 = (uint32_t)__bfloat16_as_ushort(h2) | ((uint32_t)__bfloat16_as_ushort(h3) << 16);
    lp0 = (uint32_t)__bfloat16_as_ushort(l0) | ((uint32_t)__bfloat16_as_ushort(l1) << 16);
    lp1 = (uint32_t)__bfloat16_as_ushort(l2) | ((uint32_t)__bfloat16_as_ushort(l3) << 16);
}

// ---------------------------------------------------------------------------
// Kernel 1: fused prep.
//  blockIdx.x <  64 : new_state via HMMA bf16x3. CTA = (model m = x>>2, row
//                     tile b0 = (x&3)*128). Tile 128 rows x 128 h, K = 144
//                     ([state | phi] concat), all-resident smem. tanh epilogue
//                     writes g_nsh/g_nsl/tail + ssq.
//  blockIdx.x >= 64 : trajectory hi/lo split + tsq (32 rows per CTA).
// 256 threads everywhere.
// smem (MMA blocks): SH[128r x 304B] SL | WH[144k x 272B] WL | ssq[128]
// Strides 304B (shift 12 banks/row) and 272B (4 banks/row) are LDSM
// conflict-free; no XOR swizzle needed.
// ---------------------------------------------------------------------------
#define PS_STRIDE 304
#define PW_STRIDE 272
#define POFF_SL 38912
#define POFF_WH 77824
#define POFF_WL 116992
#define POFF_SSQ 156160
#define PREP_SMEM 156672

__global__ __launch_bounds__(256) void prep_kernel(
    const float* __restrict__ phi, const float* __restrict__ state,
    const float* __restrict__ A,   const float* __restrict__ Bin,
    const float* __restrict__ tj,  float* __restrict__ tail)
{
    const int tid = threadIdx.x;
    if (blockIdx.x >= 64) {
        // ---- trajectory part: 128 CTAs x 32 rows
        const int blk = blockIdx.x - 64;
        const int wrp = tid >> 5;
        const int lid = tid & 31;
#pragma unroll
        for (int rr = 0; rr < 4; rr++) {
            const int row = blk * 32 + wrp * 4 + rr;
            float4 v = reinterpret_cast<const float4*>(tj)[row * 32 + lid];
            uint32_t hp0, hp1, lp0, lp1;
            split4(v, hp0, hp1, lp0, lp1);
            uint32_t* oh = reinterpret_cast<uint32_t*>(g_tjh) + row * 64 + lid * 2;
            uint32_t* ol = reinterpret_cast<uint32_t*>(g_tjl) + row * 64 + lid * 2;
            oh[0] = hp0; oh[1] = hp1;
            ol[0] = lp0; ol[1] = lp1;
            float s = v.x*v.x + v.y*v.y + v.z*v.z + v.w*v.w;
#pragma unroll
            for (int o = 16; o > 0; o >>= 1) s += __shfl_xor_sync(0xFFFFFFFFu, s, o);
            if (lid == 0) g_tsq[row] = s;
        }
        return;
    }

    // ---- new_state MMA part
    extern __shared__ __align__(1024) char smem[];
    const uint32_t sb = smem_u32(smem);
    const int m  = blockIdx.x >> 2;
    const int b0 = (blockIdx.x & 3) * 128;
    const int wid = tid >> 5;
    const int lid = tid & 31;
    const int warp_m = (wid >> 2) * 64;
    const int warp_n = (wid & 3) * 32;

    if (tid < 128) reinterpret_cast<float*>(smem + POFF_SSQ)[tid] = 0.0f;

    // fill state tile [r][k0..127] (+ phi at k128..143), hi & lo
    {
        const float4* s4 = reinterpret_cast<const float4*>(state);
        for (int i = tid; i < 128 * 32; i += 256) {
            int r = i >> 5, c4 = i & 31;
            float4 v = s4[(b0 + r) * 32 + c4];
            uint32_t h0, h1, l0, l1;
            split4(v, h0, h1, l0, l1);
            uint32_t off = (uint32_t)r * PS_STRIDE + (uint32_t)c4 * 8;
            *reinterpret_cast<uint2*>(smem + off)           = make_uint2(h0, h1);
            *reinterpret_cast<uint2*>(smem + POFF_SL + off) = make_uint2(l0, l1);
        }
        const float4* p4 = reinterpret_cast<const float4*>(phi);
        for (int i = tid; i < 128 * 4; i += 256) {
            int r = i >> 2, c4 = i & 3;
            float4 v = p4[(b0 + r) * 4 + c4];
            uint32_t h0, h1, l0, l1;
            split4(v, h0, h1, l0, l1);
            uint32_t off = (uint32_t)r * PS_STRIDE + 256u + (uint32_t)c4 * 8;
            *reinterpret_cast<uint2*>(smem + off)           = make_uint2(h0, h1);
            *reinterpret_cast<uint2*>(smem + POFF_SL + off) = make_uint2(l0, l1);
        }
        // weights: A_m [d][h] rows 0..127, Bin_m [p][h] rows 128..143
        const float4* a4 = reinterpret_cast<const float4*>(A) + (size_t)m * 4096;
        for (int i = tid; i < 128 * 32; i += 256) {
            int d = i >> 5, c4 = i & 31;
            float4 v = a4[d * 32 + c4];
            uint32_t h0, h1, l0, l1;
            split4(v, h0, h1, l0, l1);
            uint32_t off = (uint32_t)d * PW_STRIDE + (uint32_t)c4 * 8;
            *reinterpret_cast<uint2*>(smem + POFF_WH + off) = make_uint2(h0, h1);
            *reinterpret_cast<uint2*>(smem + POFF_WL + off) = make_uint2(l0, l1);
        }
        const float4* b4 = reinterpret_cast<const float4*>(Bin) + (size_t)m * 512;
        for (int i = tid; i < 16 * 32; i += 256) {
            int p = i >> 5, c4 = i & 31;
            float4 v = b4[p * 32 + c4];
            uint32_t h0, h1, l0, l1;
            split4(v, h0, h1, l0, l1);
            uint32_t off = (uint32_t)(128 + p) * PW_STRIDE + (uint32_t)c4 * 8;
            *reinterpret_cast<uint2*>(smem + POFF_WH + off) = make_uint2(h0, h1);
            *reinterpret_cast<uint2*>(smem + POFF_WL + off) = make_uint2(l0, l1);
        }
    }
    __syncthreads();

    float d[4][4][4];
#pragma unroll
    for (int a = 0; a < 4; a++)
#pragma unroll
        for (int b = 0; b < 4; b++)
#pragma unroll
            for (int c = 0; c < 4; c++) d[a][b][c] = 0.0f;

    const uint32_t aRow  = (uint32_t)(warp_m + (lid & 15)) * PS_STRIDE + ((uint32_t)(lid >> 4) & 1) * 16u;
    const uint32_t bKrow = (uint32_t)(lid & 15) * PW_STRIDE;
    const uint32_t bNcol = ((uint32_t)warp_n + (((uint32_t)lid >> 4) & 1) * 8u) * 2u;

#pragma unroll
    for (int ks = 0; ks < 9; ks++) {
        uint32_t bqh[2][4], bql[2][4];
#pragma unroll
        for (int np = 0; np < 2; np++) {
            const uint32_t bo = sb + POFF_WH + (uint32_t)ks * 16u * PW_STRIDE
                              + bKrow + bNcol + (uint32_t)np * 32u;
            ldsm4t(bqh[np], bo);
            ldsm4t(bql[np], bo + (POFF_WL - POFF_WH));
        }
#pragma unroll
        for (int mt = 0; mt < 4; mt++) {
            uint32_t ah[4], al[4];
            const uint32_t ao = sb + aRow + (uint32_t)mt * 16u * PS_STRIDE + (uint32_t)ks * 32u;
            ldsm4(ah, ao);
            ldsm4(al, ao + POFF_SL);
#pragma unroll
            for (int nt = 0; nt < 4; nt++) {
                const uint32_t* bh = &bqh[nt >> 1][(nt & 1) * 2];
                const uint32_t* bl = &bql[nt >> 1][(nt & 1) * 2];
                mma_bf16(d[mt][nt], ah, bh);
                mma_bf16(d[mt][nt], ah, bl);
                mma_bf16(d[mt][nt], al, bh);
            }
        }
    }

    // ---- tanh epilogue: hi/lo/tail writes + ssq reduction
    float* ssq_s = reinterpret_cast<float*>(smem + POFF_SSQ);
#pragma unroll
    for (int mt = 0; mt < 4; mt++) {
        const int lr  = warp_m + mt * 16 + (lid >> 2);
        const int rg0 = (b0 + lr) * M_ + m;
        const int rg1 = (b0 + lr + 8) * M_ + m;
        float s0 = 0.0f, s1 = 0.0f;
#pragma unroll
        for (int nt = 0; nt < 4; nt++) {
            const int lc = warp_n + nt * 8 + (lid & 3) * 2;
            float v0 = fast_tanh(d[mt][nt][0]);
            float v1 = fast_tanh(d[mt][nt][1]);
            float v2 = fast_tanh(d[mt][nt][2]);
            float v3 = fast_tanh(d[mt][nt][3]);
            s0 += v0 * v0 + v1 * v1;
            s1 += v2 * v2 + v3 * v3;
            __nv_bfloat16 h0 = __float2bfloat16_rn(v0), h1 = __float2bfloat16_rn(v1);
            __nv_bfloat16 h2 = __float2bfloat16_rn(v2), h3 = __float2bfloat16_rn(v3);
            uint32_t hp0 = (uint32_t)__bfloat16_as_ushort(h0) | ((uint32_t)__bfloat16_as_ushort(h1) << 16);
            uint32_t hp1 = (uint32_t)__bfloat16_as_ushort(h2) | ((uint32_t)__bfloat16_as_ushort(h3) << 16);
            __nv_bfloat16 q0 = __float2bfloat16_rn(v0 - __bfloat162float(h0));
            __nv_bfloat16 q1 = __float2bfloat16_rn(v1 - __bfloat162float(h1));
            __nv_bfloat16 q2 = __float2bfloat16_rn(v2 - __bfloat162float(h2));
            __nv_bfloat16 q3 = __float2bfloat16_rn(v3 - __bfloat162float(h3));
            uint32_t lp0 = (uint32_t)__bfloat16_as_ushort(q0) | ((uint32_t)__bfloat16_as_ushort(q1) << 16);
            uint32_t lp1 = (uint32_t)__bfloat16_as_ushort(q2) | ((uint32_t)__bfloat16_as_ushort(q3) << 16);
            *reinterpret_cast<uint32_t*>(g_nsh + (size_t)rg0 * D_ + lc) = hp0;
            *reinterpret_cast<uint32_t*>(g_nsh + (size_t)rg1 * D_ + lc) = hp1;
            *reinterpret_cast<uint32_t*>(g_nsl + (size_t)rg0 * D_ + lc) = lp0;
            *reinterpret_cast<uint32_t*>(g_nsl + (size_t)rg1 * D_ + lc) = lp1;
            if (tail) {
                *reinterpret_cast<float2*>(tail + (size_t)rg0 * D_ + lc) = make_float2(v0, v1);
                *reinterpret_cast<float2*>(tail + (size_t)rg1 * D_ + lc) = make_float2(v2, v3);
            }
        }
        s0 += __shfl_xor_sync(0xFFFFFFFFu, s0, 1);
        s0 += __shfl_xor_sync(0xFFFFFFFFu, s0, 2);
        s1 += __shfl_xor_sync(0xFFFFFFFFu, s1, 1);
        s1 += __shfl_xor_sync(0xFFFFFFFFu, s1, 2);
        if ((lid & 3) == 0) {
            atomicAdd(&ssq_s[lr], s0);
            atomicAdd(&ssq_s[lr + 8], s1);
        }
    }
    __syncthreads();
    if (tid < 128) g_ssq[(b0 + tid) * M_ + m] = ssq_s[tid];
}

// ---------------------------------------------------------------------------
// Kernel 2: HMMA (bf16 hi/lo x3) GEMM + fused RBF epilogue.
// (unchanged from round 6: 78.5us, protect it)
// ---------------------------------------------------------------------------
#define STG_STRIDE 32768
#define TILE_STRIDE 8192
#define OFF_SSQ  98304
#define OFF_TSQ  98816
#define SMEM_BYTES 99328

__global__ __launch_bounds__(256, 2) void sim_mma_kernel(float* __restrict__ out)
{
    extern __shared__ __align__(1024) char smem[];
    const uint32_t sb = smem_u32(smem);
    const int tid = threadIdx.x;
    const int wid = tid >> 5;
    const int lid = tid & 31;
    const int warp_m = (wid >> 2) * 64;
    const int warp_n = (wid & 3) * 32;
    const int r0 = blockIdx.y * TMT;
    const int t0 = blockIdx.x * TNT;

    const __nv_bfloat16* srcs[4] = {
        g_nsh + (size_t)r0 * D_, g_nsl + (size_t)r0 * D_,
        g_tjh + (size_t)t0 * D_, g_tjl + (size_t)t0 * D_ };

    auto fill = [&](int st) {
        const uint32_t sbase = sb + (uint32_t)(st % 3) * STG_STRIDE;
#pragma unroll
        for (int t = 0; t < 8; t++) {
            const int tile = t >> 1;
            const int rem  = ((t & 1) << 8) + tid;     // 0..511
            const int r = rem >> 2, c = rem & 3;
            const uint32_t slot = (uint32_t)(c ^ (r & 3) ^ (((r >> 2) & 1) << 1));
            const uint32_t dst = sbase + (uint32_t)tile * TILE_STRIDE
                               + (uint32_t)r * 64u + (slot << 4);
            cpasync16(dst, srcs[tile] + r * D_ + st * 32 + c * 8);
        }
    };

    if (tid < 128) reinterpret_cast<float*>(smem + OFF_SSQ)[tid] = g_ssq[r0 + tid];
    else           reinterpret_cast<float*>(smem + OFF_TSQ)[tid - 128] = g_tsq[t0 + tid - 128];

    fill(0); CP_COMMIT();
    fill(1); CP_COMMIT();

    float d[4][4][4];
#pragma unroll
    for (int a = 0; a < 4; a++)
#pragma unroll
        for (int b = 0; b < 4; b++)
#pragma unroll
            for (int c = 0; c < 4; c++) d[a][b][c] = 0.0f;

    uint32_t rowOffA[4], rowOffB[2];
    uint32_t rxA, rxB;
    {
        const int ra = warp_m + (lid & 15);
        rxA = (uint32_t)((ra & 3) ^ (((ra >> 2) & 1) << 1));
#pragma unroll
        for (int mt = 0; mt < 4; mt++) rowOffA[mt] = (uint32_t)(ra + mt * 16) * 64u;
        const int rb = warp_n + ((lid & 16) >> 1) + (lid & 7);
        rxB = (uint32_t)((rb & 3) ^ (((rb >> 2) & 1) << 1));
#pragma unroll
        for (int np = 0; np < 2; np++) rowOffB[np] = (uint32_t)(rb + np * 16) * 64u;
    }
    const uint32_t aSel = (lid >> 4) & 1;
    const uint32_t bSel = (lid >> 3) & 1;

#pragma unroll
    for (int st = 0; st < 4; st++) {
        if (st < 3) { CP_WAIT(1); } else { CP_WAIT(0); }
        __syncthreads();
        if (st + 2 < 4) { fill(st + 2); CP_COMMIT(); }

        const uint32_t sbs = sb + (uint32_t)(st % 3) * STG_STRIDE;
#pragma unroll
        for (int ks = 0; ks < 2; ks++) {
            const uint32_t cA = (uint32_t)(ks * 2) + aSel;
            const uint32_t cB = (uint32_t)(ks * 2) + bSel;
            uint32_t bqh[2][4], bql[2][4];
#pragma unroll
            for (int np = 0; np < 2; np++) {
                const uint32_t bo = sbs + 2u * TILE_STRIDE + rowOffB[np] + (((cB ^ rxB)) << 4);
                ldsm4(bqh[np], bo);
                ldsm4(bql[np], bo + TILE_STRIDE);
            }
#pragma unroll
            for (int mt = 0; mt < 4; mt++) {
                uint32_t ah[4], al[4];
                const uint32_t ao = sbs + rowOffA[mt] + (((cA ^ rxA)) << 4);
                ldsm4(ah, ao);
                ldsm4(al, ao + TILE_STRIDE);
#pragma unroll
                for (int nt = 0; nt < 4; nt++) {
                    const uint32_t* bh = &bqh[nt >> 1][(nt & 1) * 2];
                    const uint32_t* bl = &bql[nt >> 1][(nt & 1) * 2];
                    mma_bf16(d[mt][nt], ah, bh);
                    mma_bf16(d[mt][nt], ah, bl);
                    mma_bf16(d[mt][nt], al, bh);
                }
            }
        }
    }

    const float* s_ssq = reinterpret_cast<const float*>(smem + OFF_SSQ);
    const float* s_tsq = reinterpret_cast<const float*>(smem + OFF_TSQ);
    const float NL2E = -1.4426950408889634f;
    const float SC64 = 5.421010862427522e-20f;   // 2^-64

#pragma unroll
    for (int mt = 0; mt < 4; mt++) {
        const int lr = warp_m + mt * 16 + (lid >> 2);
        const float sq0 = s_ssq[lr];
        const float sq1 = s_ssq[lr + 8];
        float* row0 = out + (size_t)(r0 + lr) * T_ + t0;
        float* row1 = row0 + (size_t)8 * T_;
#pragma unroll
        for (int nt = 0; nt < 4; nt++) {
            const int lc = warp_n + nt * 8 + (lid & 3) * 2;
            const float tq0 = s_tsq[lc], tq1 = s_tsq[lc + 1];
            float in[4] = { sq0 + tq0, sq0 + tq1, sq1 + tq0, sq1 + tq1 };
            float o[4];
#pragma unroll
            for (int j = 0; j < 4; j++) {
                float dd = fmaf(-2.0f, d[mt][nt][j], in[j]);
                dd = fmaxf(dd, 0.0f);
                float t = NL2E * dd;
                float tb = t, sc = 1.0f;
                if (t < -80.0f) { tb = t + 64.0f; sc = SC64; }
                o[j] = ex2a(tb) * sc;
            }
            *reinterpret_cast<float2*>(row0 + lc) = make_float2(o[0], o[1]);
            *reinterpret_cast<float2*>(row1 + lc) = make_float2(o[2], o[3]);
        }
    }
}

// ---------------------------------------------------------------------------
extern "C" void kernel_launch(void* const* d_in, const int* in_sizes, int n_in,
                              void* d_out, int out_size) {
    const float *phi = nullptr, *state = nullptr, *traj = nullptr, *A = nullptr, *Bin = nullptr;
    for (int i = 0; i < n_in; i++) {
        switch (in_sizes[i]) {
            case B_ * P_:      phi   = (const float*)d_in[i]; break;  // 8192
            case B_ * D_:      state = (const float*)d_in[i]; break;  // 65536
            case T_ * D_:      traj  = (const float*)d_in[i]; break;  // 524288
            case M_ * D_ * D_: A     = (const float*)d_in[i]; break;  // 262144
            case M_ * P_ * D_: Bin   = (const float*)d_in[i]; break;  // 32768
        }
    }
    float* out = (float*)d_out;
    const long long SIMSZ = (long long)R_ * T_;
    const long long NSSZ  = (long long)R_ * D_;
    float* tail = ((long long)out_size >= SIMSZ + NSSZ) ? out + SIMSZ : nullptr;

    cudaFuncSetAttribute(prep_kernel, cudaFuncAttributeMaxDynamicSharedMemorySize, PREP_SMEM);
    prep_kernel<<<192, 256, PREP_SMEM>>>(phi, state, A, Bin, traj, tail);

    cudaFuncSetAttribute(sim_mma_kernel, cudaFuncAttributeMaxDynamicSharedMemorySize, SMEM_BYTES);
    sim_mma_kernel<<<dim3(T_ / TNT, R_ / TMT), 256, SMEM_BYTES>>>(out);
}